// round 5
// baseline (speedup 1.0000x reference)
#include <cuda_runtime.h>

// VN_Attention: B=8, C=64, U=3, N=512
// R5: two kernels.
//  K1: per-(b,c) channel projections -> global scratch (q pre-scaled by
//      C^-0.5*log2e, k/v stored as 48B pair-interleaved rows).
//  K2: attention only. grid (512,4), 128 threads, 1 query/thread ->
//      55 warps/SM (vs 27.7 in the fused kernel) to overlap the balanced
//      MUFU(30us)/FMA(26us)/LDS(22us) pipe floors. No projection duplication.

#define BB 8
#define CC 64
#define UU 3
#define NN 512
#define SLAB (UU * NN)          // 1536 floats
#define SLAB2 (SLAB / 2)        // 768 ull
#define NSLAB (BB * CC)         // 512
#define KVROW 12                // floats per j-pair row
#define KVSLAB (256 * KVROW)    // 3072 floats per slab

typedef unsigned long long ull;

__device__ float qg[NSLAB * SLAB];      // 3 MB, [slab][u][n], pre-scaled
__device__ float kvg[NSLAB * KVSLAB];   // 6 MB, [slab][jpair][12]

__device__ __forceinline__ float ex2_approx(float x) {
    float r;
    asm("ex2.approx.ftz.f32 %0, %1;" : "=f"(r) : "f"(x));
    return r;
}
__device__ __forceinline__ ull pack2(float lo, float hi) {
    ull r; asm("mov.b64 %0, {%1, %2};" : "=l"(r) : "f"(lo), "f"(hi)); return r;
}
__device__ __forceinline__ void unpack2(ull v, float& lo, float& hi) {
    asm("mov.b64 {%0, %1}, %2;" : "=f"(lo), "=f"(hi) : "l"(v));
}
__device__ __forceinline__ ull fma2(ull a, ull b, ull c) {
    ull d; asm("fma.rn.f32x2 %0, %1, %2, %3;" : "=l"(d) : "l"(a), "l"(b), "l"(c)); return d;
}
__device__ __forceinline__ ull mul2(ull a, ull b) {
    ull d; asm("mul.rn.f32x2 %0, %1, %2;" : "=l"(d) : "l"(a), "l"(b)); return d;
}
__device__ __forceinline__ ull add2(ull a, ull b) {
    ull d; asm("add.rn.f32x2 %0, %1, %2;" : "=l"(d) : "l"(a), "l"(b)); return d;
}

// ---------------- K1: projections ----------------
__global__ __launch_bounds__(256, 4)
void vn_proj_kernel(const float* __restrict__ x,
                    const float* __restrict__ Wq,
                    const float* __restrict__ Wk,
                    const float* __restrict__ Wv)
{
    __shared__ float wq[CC], wk[CC], wv[CC];
    const int tid = threadIdx.x;
    const int bc = blockIdx.x;
    const int b = bc >> 6;
    const int c = bc & 63;

    if (tid < CC) {
        wq[tid] = Wq[c * CC + tid];
        wk[tid] = Wk[c * CC + tid];
        wv[tid] = Wv[c * CC + tid];
    }
    __syncthreads();

    ull aq[3], ak[3], av[3];
    #pragma unroll
    for (int r = 0; r < 3; ++r) { aq[r] = 0ull; ak[r] = 0ull; av[r] = 0ull; }

    const ull* xb = reinterpret_cast<const ull*>(x) + (size_t)b * CC * SLAB2;
    #pragma unroll 4
    for (int cp = 0; cp < CC; ++cp) {
        const ull* xr = xb + cp * SLAB2;
        const ull wq2 = pack2(wq[cp], wq[cp]);
        const ull wk2 = pack2(wk[cp], wk[cp]);
        const ull wv2 = pack2(wv[cp], wv[cp]);
        #pragma unroll
        for (int r = 0; r < 3; ++r) {
            ull xv = xr[tid + r * 256];
            aq[r] = fma2(xv, wq2, aq[r]);
            ak[r] = fma2(xv, wk2, ak[r]);
            av[r] = fma2(xv, wv2, av[r]);
        }
    }

    const float qs = 0.125f * 1.44269504088896340736f;  // C^-0.5 * log2(e)
    const ull qs2 = pack2(qs, qs);
    ull* qgU  = reinterpret_cast<ull*>(qg)  + (size_t)bc * SLAB2;
    ull* kvgU = reinterpret_cast<ull*>(kvg) + (size_t)bc * (KVSLAB / 2);
    #pragma unroll
    for (int r = 0; r < 3; ++r) {
        const int p = tid + r * 256;      // float2 index in [0,768)
        qgU[p] = mul2(aq[r], qs2);
        const int u  = p >> 8;            // 0..2
        const int pp = p & 255;           // j-pair index
        kvgU[pp * 6 + u]     = ak[r];
        kvgU[pp * 6 + 3 + u] = av[r];
    }
}

// ---------------- K2: attention ----------------
__global__ __launch_bounds__(128, 14)
void vn_attn_kernel(const float* __restrict__ x,
                    float* __restrict__ out)
{
    __shared__ __align__(16) float kv[KVSLAB];   // 12 KB

    const int tid = threadIdx.x;
    const int bc = blockIdx.x;
    const int i = blockIdx.y * 128 + tid;        // this thread's query

    // Load kv slab into smem (straight copy, layout preserved).
    const float4* src = reinterpret_cast<const float4*>(kvg + (size_t)bc * KVSLAB);
    float4* dst = reinterpret_cast<float4*>(kv);
    #pragma unroll
    for (int t = 0; t < 6; ++t)
        dst[tid + t * 128] = src[tid + t * 128];

    // Load this thread's (pre-scaled) query, duplicate into packs.
    const float* qb = qg + (size_t)bc * SLAB;
    const float ql0 = qb[0 * NN + i];
    const float ql1 = qb[1 * NN + i];
    const float ql2 = qb[2 * NN + i];
    const ull q0 = pack2(ql0, ql0);
    const ull q1 = pack2(ql1, ql1);
    const ull q2 = pack2(ql2, ql2);
    __syncthreads();

    ull s = 0ull, a0 = 0ull, a1 = 0ull, a2 = 0ull;

    const ulonglong2* kvrow = reinterpret_cast<const ulonglong2*>(kv);
    #pragma unroll 4
    for (int p = 0; p < 256; ++p) {
        // row p: A=(k0,k1), B=(k2,v0), C=(v1,v2)  (each component a j-pair)
        const ulonglong2 A = kvrow[p * 3 + 0];
        const ulonglong2 B = kvrow[p * 3 + 1];
        const ulonglong2 C = kvrow[p * 3 + 2];

        ull d = fma2(q0, A.x, fma2(q1, A.y, mul2(q2, B.x)));
        float dl, dh;
        unpack2(d, dl, dh);
        const ull e = pack2(ex2_approx(dl), ex2_approx(dh));

        s  = add2(s, e);
        a0 = fma2(e, B.y, a0);
        a1 = fma2(e, C.x, a1);
        a2 = fma2(e, C.y, a2);
    }

    float lo, hi, sf;
    unpack2(s, lo, hi); sf = lo + hi;
    const float inv = __fdividef(1.f, sf);

    float r0, r1, r2;
    unpack2(a0, lo, hi); r0 = lo + hi;
    unpack2(a1, lo, hi); r1 = lo + hi;
    unpack2(a2, lo, hi); r2 = lo + hi;

    const size_t base = (size_t)bc * SLAB;
    out[base + 0 * NN + i] = x[base + 0 * NN + i] + r0 * inv;
    out[base + 1 * NN + i] = x[base + 1 * NN + i] + r1 * inv;
    out[base + 2 * NN + i] = x[base + 2 * NN + i] + r2 * inv;
}

extern "C" void kernel_launch(void* const* d_in, const int* in_sizes, int n_in,
                              void* d_out, int out_size) {
    const float* x  = (const float*)d_in[0];
    const float* Wq = (const float*)d_in[1];
    const float* Wk = (const float*)d_in[2];
    const float* Wv = (const float*)d_in[3];
    float* out = (float*)d_out;

    vn_proj_kernel<<<NSLAB, 256>>>(x, Wq, Wk, Wv);
    dim3 grid2(NSLAB, 4);
    vn_attn_kernel<<<grid2, 128>>>(x, out);
}

// round 7
// speedup vs baseline: 1.1026x; 1.1026x over previous
#include <cuda_runtime.h>
#include <cstdint>

// VN_Attention: B=8, C=64, U=3, N=512
// R7 (= R6 + missing <cstdint>):
//  K1: projections at high parallelism (grid (512,3), u-plane per CTA).
//  K2: attention, q=2/thread (LDS amortized) + j-split=2 across a 2-CTA
//      cluster; partials exchanged via DSMEM, no reduce kernel.

#define BB 8
#define CC 64
#define UU 3
#define NN 512
#define SLAB (UU * NN)          // 1536 floats
#define SLAB2 (SLAB / 2)        // 768 ull
#define NSLAB (BB * CC)         // 512
#define KVSLAB (256 * 12)       // 3072 floats per slab (j-pair rows of 12)

typedef unsigned long long ull;
typedef unsigned int u32;

__device__ float qg[NSLAB * SLAB];      // 3 MB, pre-scaled q, [slab][u][n]
__device__ float kvg[NSLAB * KVSLAB];   // 6 MB, [slab][jpair][12]

__device__ __forceinline__ float ex2_approx(float x) {
    float r; asm("ex2.approx.ftz.f32 %0, %1;" : "=f"(r) : "f"(x)); return r;
}
__device__ __forceinline__ ull pack2(float lo, float hi) {
    ull r; asm("mov.b64 %0, {%1, %2};" : "=l"(r) : "f"(lo), "f"(hi)); return r;
}
__device__ __forceinline__ void unpack2(ull v, float& lo, float& hi) {
    asm("mov.b64 {%0, %1}, %2;" : "=f"(lo), "=f"(hi) : "l"(v));
}
__device__ __forceinline__ ull fma2(ull a, ull b, ull c) {
    ull d; asm("fma.rn.f32x2 %0, %1, %2, %3;" : "=l"(d) : "l"(a), "l"(b), "l"(c)); return d;
}
__device__ __forceinline__ ull mul2(ull a, ull b) {
    ull d; asm("mul.rn.f32x2 %0, %1, %2;" : "=l"(d) : "l"(a), "l"(b)); return d;
}
__device__ __forceinline__ ull add2(ull a, ull b) {
    ull d; asm("add.rn.f32x2 %0, %1, %2;" : "=l"(d) : "l"(a), "l"(b)); return d;
}
__device__ __forceinline__ u32 smem_u32(const void* p) {
    u32 a;
    asm("{ .reg .u64 t; cvta.to.shared.u64 t, %1; cvt.u32.u64 %0, t; }" : "=r"(a) : "l"(p));
    return a;
}

// ---------------- K1: projections (grid (512, 3), u-plane per CTA) ----------
__global__ __launch_bounds__(256, 6)
void vn_proj_kernel(const float* __restrict__ x,
                    const float* __restrict__ Wq,
                    const float* __restrict__ Wk,
                    const float* __restrict__ Wv)
{
    __shared__ float wq[CC], wk[CC], wv[CC];
    const int tid = threadIdx.x;
    const int bc = blockIdx.x;
    const int b = bc >> 6;
    const int c = bc & 63;
    const int u = blockIdx.y;          // 0..2

    if (tid < CC) {
        wq[tid] = Wq[c * CC + tid];
        wk[tid] = Wk[c * CC + tid];
        wv[tid] = Wv[c * CC + tid];
    }
    __syncthreads();

    ull aq = 0ull, ak = 0ull, av = 0ull;
    const int p = u * 256 + tid;       // float2 position in [0,768)
    const ull* xb = reinterpret_cast<const ull*>(x) + (size_t)b * CC * SLAB2 + p;

    #pragma unroll 8
    for (int cp = 0; cp < CC; ++cp) {
        const ull xv = xb[cp * SLAB2];
        const ull wq2 = pack2(wq[cp], wq[cp]);
        const ull wk2 = pack2(wk[cp], wk[cp]);
        const ull wv2 = pack2(wv[cp], wv[cp]);
        aq = fma2(xv, wq2, aq);
        ak = fma2(xv, wk2, ak);
        av = fma2(xv, wv2, av);
    }

    const float qs = 0.125f * 1.44269504088896340736f;  // C^-0.5 * log2(e)
    ull* qgU  = reinterpret_cast<ull*>(qg)  + (size_t)bc * SLAB2;
    ull* kvgU = reinterpret_cast<ull*>(kvg) + (size_t)bc * (KVSLAB / 2);
    qgU[p] = mul2(aq, pack2(qs, qs));
    kvgU[tid * 6 + u]     = ak;        // k component u, j-pair tid
    kvgU[tid * 6 + 3 + u] = av;        // v component u
}

// ---------------- K2: attention, 2-CTA cluster over j-halves ---------------
__global__ __launch_bounds__(256, 5) __cluster_dims__(2, 1, 1)
void vn_attn_kernel(const float* __restrict__ x,
                    float* __restrict__ out)
{
    __shared__ __align__(16) float kv[KVSLAB / 2];   // 6 KB: 128 j-pair rows
    __shared__ __align__(16) float4 pbuf[NN];        // 8 KB: per-query partials

    const int tid = threadIdx.x;
    const int bc = blockIdx.x >> 1;
    u32 z;                                           // j-half == cluster rank
    asm("mov.u32 %0, %%cluster_ctarank;" : "=r"(z));

    // Load this j-half's kv rows (1536 floats = 384 float4).
    {
        const float4* src = reinterpret_cast<const float4*>(
            kvg + (size_t)bc * KVSLAB + z * (KVSLAB / 2));
        float4* dst = reinterpret_cast<float4*>(kv);
        dst[tid] = src[tid];
        if (tid < 128) dst[tid + 256] = src[tid + 256];
    }

    // Queries i0 = tid, i1 = tid + 256 (pre-scaled q from K1).
    const float* qb = qg + (size_t)bc * SLAB;
    const int i0 = tid, i1 = tid + 256;
    const ull q00 = pack2(qb[0 * NN + i0], qb[0 * NN + i0]);
    const ull q01 = pack2(qb[1 * NN + i0], qb[1 * NN + i0]);
    const ull q02 = pack2(qb[2 * NN + i0], qb[2 * NN + i0]);
    const ull q10 = pack2(qb[0 * NN + i1], qb[0 * NN + i1]);
    const ull q11 = pack2(qb[1 * NN + i1], qb[1 * NN + i1]);
    const ull q12 = pack2(qb[2 * NN + i1], qb[2 * NN + i1]);
    __syncthreads();

    ull s0 = 0ull, a00 = 0ull, a01 = 0ull, a02 = 0ull;
    ull s1 = 0ull, a10 = 0ull, a11 = 0ull, a12 = 0ull;

    const ulonglong2* kvrow = reinterpret_cast<const ulonglong2*>(kv);
    #pragma unroll 4
    for (int p = 0; p < 128; ++p) {
        const ulonglong2 A = kvrow[p * 3 + 0];   // (k0,k1) j-pairs
        const ulonglong2 B = kvrow[p * 3 + 1];   // (k2,v0)
        const ulonglong2 C = kvrow[p * 3 + 2];   // (v1,v2)

        ull d0 = fma2(q00, A.x, fma2(q01, A.y, mul2(q02, B.x)));
        ull d1 = fma2(q10, A.x, fma2(q11, A.y, mul2(q12, B.x)));

        float d0l, d0h, d1l, d1h;
        unpack2(d0, d0l, d0h);
        unpack2(d1, d1l, d1h);
        const ull e0 = pack2(ex2_approx(d0l), ex2_approx(d0h));
        const ull e1 = pack2(ex2_approx(d1l), ex2_approx(d1h));

        s0 = add2(s0, e0);
        a00 = fma2(e0, B.y, a00);
        a01 = fma2(e0, C.x, a01);
        a02 = fma2(e0, C.y, a02);

        s1 = add2(s1, e1);
        a10 = fma2(e1, B.y, a10);
        a11 = fma2(e1, C.x, a11);
        a12 = fma2(e1, C.y, a12);
    }

    // Reduce packed halves -> per-query partial (s, a0, a1, a2).
    float lo, hi;
    float4 p0, p1;
    unpack2(s0, lo, hi);  p0.x = lo + hi;
    unpack2(a00, lo, hi); p0.y = lo + hi;
    unpack2(a01, lo, hi); p0.z = lo + hi;
    unpack2(a02, lo, hi); p0.w = lo + hi;
    unpack2(s1, lo, hi);  p1.x = lo + hi;
    unpack2(a10, lo, hi); p1.y = lo + hi;
    unpack2(a11, lo, hi); p1.z = lo + hi;
    unpack2(a12, lo, hi); p1.w = lo + hi;
    pbuf[i0] = p0;
    pbuf[i1] = p1;

    // Cluster barrier: partials visible to peer.
    asm volatile("barrier.cluster.arrive.aligned;" ::: "memory");
    asm volatile("barrier.cluster.wait.aligned;" ::: "memory");

    // Epilogue: this CTA finalizes queries [z*256, z*256+256).
    const int jq = (int)z * 256 + tid;
    const float4 mine = pbuf[jq];
    float4 theirs;
    {
        u32 laddr = smem_u32(&pbuf[jq]);
        u32 raddr;
        asm("mapa.shared::cluster.u32 %0, %1, %2;" : "=r"(raddr) : "r"(laddr), "r"(z ^ 1u));
        asm("ld.shared::cluster.v4.f32 {%0,%1,%2,%3}, [%4];"
            : "=f"(theirs.x), "=f"(theirs.y), "=f"(theirs.z), "=f"(theirs.w)
            : "r"(raddr));
    }

    const float inv = __fdividef(1.f, mine.x + theirs.x);
    const size_t base = (size_t)bc * SLAB;
    out[base + 0 * NN + jq] = x[base + 0 * NN + jq] + (mine.y + theirs.y) * inv;
    out[base + 1 * NN + jq] = x[base + 1 * NN + jq] + (mine.z + theirs.z) * inv;
    out[base + 2 * NN + jq] = x[base + 2 * NN + jq] + (mine.w + theirs.w) * inv;

    // Keep smem alive until peer finished reading.
    asm volatile("barrier.cluster.arrive.aligned;" ::: "memory");
    asm volatile("barrier.cluster.wait.aligned;" ::: "memory");
}

extern "C" void kernel_launch(void* const* d_in, const int* in_sizes, int n_in,
                              void* d_out, int out_size) {
    const float* x  = (const float*)d_in[0];
    const float* Wq = (const float*)d_in[1];
    const float* Wk = (const float*)d_in[2];
    const float* Wv = (const float*)d_in[3];
    float* out = (float*)d_out;

    dim3 grid1(NSLAB, 3);
    vn_proj_kernel<<<grid1, 256>>>(x, Wq, Wk, Wv);
    vn_attn_kernel<<<NSLAB * 2, 256>>>(x, out);
}